// round 2
// baseline (speedup 1.0000x reference)
#include <cuda_runtime.h>
#include <cuda_bf16.h>
#include <stdint.h>

// ---------------------------------------------------------------------------
// SPMoEAdaptor fused kernel (2 soft-MoE layers + residual) for sm_103a. R2:
//  - 32 tokens/warp (2x m16 tiles) -> each B fragment feeds 2 MMAs
//  - weights packed [n][j][kk] -> 2x LDS.128 per n-tile (conflict-free, 144B row stride)
//  - gates folded into A fragments: g_e*(x@W_e) = (g_e*x)@W_e, MMA accumulates h directly
// ---------------------------------------------------------------------------

#define DD 64
#define EE 4
#define NW 264          // 256 expert cols + 4 gate cols + 4 zero pad
#define WS_U2 18        // uint2 per weight row in smem (16 payload + 2 pad = 144B)

// Prepacked weights: [layer][n][j][kk]; uint2 = {bf16x2(d=kk*16+2j,+1), bf16x2(d+8,+9)}
__device__ uint2 g_wpack[2][NW][4][4];
__device__ float g_c[2][EE][DD];   // c_e[f] = sum_d b[e,d]*W[e,d,f]

__device__ __forceinline__ uint32_t pack_bf16x2(float lo, float hi) {
    uint32_t r;
    asm("cvt.rn.bf16x2.f32 %0, %1, %2;" : "=r"(r) : "f"(hi), "f"(lo));
    return r;
}
__device__ __forceinline__ uint32_t mul_bf16x2(uint32_t a, uint32_t b) {
    uint32_t r;
    asm("mul.bf16x2 %0, %1, %2;" : "=r"(r) : "r"(a), "r"(b));
    return r;
}

// ------------------------------ prep kernel --------------------------------
__global__ void prep_kernel(const float* __restrict__ wg_a, const float* __restrict__ we_a,
                            const float* __restrict__ be_a,
                            const float* __restrict__ wg_b, const float* __restrict__ we_b,
                            const float* __restrict__ be_b) {
    const int L = blockIdx.x;
    const float* wg = L ? wg_b : wg_a;
    const float* we = L ? we_b : we_a;
    const float* be = L ? be_b : be_a;

    for (int idx = threadIdx.x; idx < NW * 16; idx += blockDim.x) {
        int n  = idx >> 4;
        int j  = (idx >> 2) & 3;
        int kk = idx & 3;
        float v[4];
#pragma unroll
        for (int h = 0; h < 4; h++) {
            int d = kk * 16 + 2 * j + (h >> 1) * 8 + (h & 1);
            float w;
            if (n < 256)        w = we[((n >> 6) * DD + d) * DD + (n & 63)]; // W_e[d][f]
            else if (n < 260)   w = wg[d * EE + (n - 256)];                  // w_gate[d][e]
            else                w = 0.0f;
            v[h] = w;
        }
        uint2 u;
        u.x = pack_bf16x2(v[0], v[1]);
        u.y = pack_bf16x2(v[2], v[3]);
        g_wpack[L][n][j][kk] = u;
    }
    for (int idx = threadIdx.x; idx < EE * DD; idx += blockDim.x) {
        int e = idx >> 6, f = idx & 63;
        float s = 0.0f;
        for (int d = 0; d < DD; d++) s += be[e * DD + d] * we[(e * DD + d) * DD + f];
        g_c[L][e][f] = s;
    }
}

// ------------------------------ MMA helpers --------------------------------
__device__ __forceinline__ void mma16816(float c[4], const uint32_t a[4], uint32_t b0, uint32_t b1) {
    asm volatile(
        "mma.sync.aligned.m16n8k16.row.col.f32.bf16.bf16.f32 "
        "{%0,%1,%2,%3}, {%4,%5,%6,%7}, {%8,%9}, {%0,%1,%2,%3};"
        : "+f"(c[0]), "+f"(c[1]), "+f"(c[2]), "+f"(c[3])
        : "r"(a[0]), "r"(a[1]), "r"(a[2]), "r"(a[3]), "r"(b0), "r"(b1));
}

__device__ __forceinline__ void softmax4(float g[4], float a, float b, float c, float d) {
    float m = fmaxf(fmaxf(a, b), fmaxf(c, d));
    float e0 = __expf(a - m), e1 = __expf(b - m), e2 = __expf(c - m), e3 = __expf(d - m);
    float inv = 1.0f / (e0 + e1 + e2 + e3);
    g[0] = e0 * inv; g[1] = e1 * inv; g[2] = e2 * inv; g[3] = e3 * inv;
}

// One full MoE layer for TWO m16 tiles (32 tokens) per warp.
__device__ __forceinline__ void moe_layer2(float h[2][8][4], const uint32_t A[2][4][4],
                                           const uint2* __restrict__ ws,
                                           const float* __restrict__ cl, int lane) {
    const int qr = lane >> 2, qc = lane & 3;
    const uint4* wl = (const uint4*)ws + qr * 9 + qc * 2;   // 9 uint4 per weight row
    const unsigned full = 0xffffffffu;
    const int qb = lane & ~3;

    // ---- gates (panel rows 256..263) ----
    float glo[2][4], ghi[2][4];
#pragma unroll
    for (int t = 0; t < 2; t++) {
        float acc[4] = {0.f, 0.f, 0.f, 0.f};
        uint4 b01 = wl[256 * 9];
        uint4 b23 = wl[256 * 9 + 1];
        mma16816(acc, A[t][0], b01.x, b01.y);
        mma16816(acc, A[t][1], b01.z, b01.w);
        mma16816(acc, A[t][2], b23.x, b23.y);
        mma16816(acc, A[t][3], b23.z, b23.w);
        float l0 = __shfl_sync(full, acc[0], qb);
        float l1 = __shfl_sync(full, acc[1], qb);
        float l2 = __shfl_sync(full, acc[0], qb + 1);
        float l3 = __shfl_sync(full, acc[1], qb + 1);
        float m0 = __shfl_sync(full, acc[2], qb);
        float m1 = __shfl_sync(full, acc[3], qb);
        float m2 = __shfl_sync(full, acc[2], qb + 1);
        float m3 = __shfl_sync(full, acc[3], qb + 1);
        softmax4(glo[t], l0, l1, l2, l3);
        softmax4(ghi[t], m0, m1, m2, m3);
    }

    // gate scalers packed bf16x2 (broadcast pair)
    uint32_t glp[2][4], ghp[2][4];
#pragma unroll
    for (int t = 0; t < 2; t++)
#pragma unroll
        for (int e = 0; e < 4; e++) {
            glp[t][e] = pack_bf16x2(glo[t][e], glo[t][e]);
            ghp[t][e] = pack_bf16x2(ghi[t][e], ghi[t][e]);
        }

#pragma unroll
    for (int t = 0; t < 2; t++)
#pragma unroll
        for (int s = 0; s < 8; s++) {
            h[t][s][0] = 0.f; h[t][s][1] = 0.f; h[t][s][2] = 0.f; h[t][s][3] = 0.f;
        }

    // ---- experts: h += (g_e * x) @ W_e, MMA-accumulated ----
#pragma unroll
    for (int e = 0; e < 4; e++) {
        uint32_t Ae[2][4][4];
#pragma unroll
        for (int t = 0; t < 2; t++)
#pragma unroll
            for (int kk = 0; kk < 4; kk++) {
                Ae[t][kk][0] = mul_bf16x2(A[t][kk][0], glp[t][e]);   // row qr
                Ae[t][kk][1] = mul_bf16x2(A[t][kk][1], ghp[t][e]);   // row qr+8
                Ae[t][kk][2] = mul_bf16x2(A[t][kk][2], glp[t][e]);
                Ae[t][kk][3] = mul_bf16x2(A[t][kk][3], ghp[t][e]);
            }
#pragma unroll
        for (int s = 0; s < 8; s++) {
            const uint4* p = wl + (e * 8 + s) * 8 * 9;
            uint4 b01 = p[0];
            uint4 b23 = p[1];
#pragma unroll
            for (int t = 0; t < 2; t++) {
                mma16816(h[t][s], Ae[t][0], b01.x, b01.y);
                mma16816(h[t][s], Ae[t][1], b01.z, b01.w);
                mma16816(h[t][s], Ae[t][2], b23.x, b23.y);
                mma16816(h[t][s], Ae[t][3], b23.z, b23.w);
            }
        }
    }

    // ---- bias correction: h -= sum_e g_e * c_e ----
#pragma unroll
    for (int s = 0; s < 8; s++) {
        int f = s * 8 + qc * 2;
#pragma unroll
        for (int e = 0; e < 4; e++) {
            float2 ce = *(const float2*)(cl + e * 64 + f);
#pragma unroll
            for (int t = 0; t < 2; t++) {
                h[t][s][0] = fmaf(-glo[t][e], ce.x, h[t][s][0]);
                h[t][s][1] = fmaf(-glo[t][e], ce.y, h[t][s][1]);
                h[t][s][2] = fmaf(-ghi[t][e], ce.x, h[t][s][2]);
                h[t][s][3] = fmaf(-ghi[t][e], ce.y, h[t][s][3]);
            }
        }
    }
}

// ------------------------------ main kernel --------------------------------
__global__ __launch_bounds__(256, 1)
void moe_main_kernel(const float* __restrict__ x, float* __restrict__ out, int Ntok) {
    extern __shared__ __align__(16) uint2 smem[];
    uint2* ws0 = smem;
    uint2* ws1 = smem + NW * WS_U2;
    float* cs  = (float*)(smem + 2 * NW * WS_U2);   // [2][256]

    for (int idx = threadIdx.x; idx < NW * 16; idx += 256) {
        int n = idx >> 4, r = idx & 15;
        ws0[n * WS_U2 + r] = ((const uint2*)g_wpack[0])[idx];
        ws1[n * WS_U2 + r] = ((const uint2*)g_wpack[1])[idx];
    }
    for (int idx = threadIdx.x; idx < 512; idx += 256)
        cs[idx] = ((const float*)g_c)[idx];
    __syncthreads();

    const int warp = threadIdx.x >> 5;
    const int lane = threadIdx.x & 31;
    const int qr = lane >> 2;
    const int qc = lane & 3;
    const int tokbase = blockIdx.x * 256 + warp * 32;

    // ---- layer 1 A fragments straight from gmem (fp32 -> bf16), 2 tiles ----
    uint32_t A1[2][4][4];
#pragma unroll
    for (int t = 0; t < 2; t++) {
        int ra = min(tokbase + t * 16 + qr, Ntok - 1);
        int rb = min(tokbase + t * 16 + qr + 8, Ntok - 1);
        const float* xa = x + (size_t)ra * DD;
        const float* xb = x + (size_t)rb * DD;
#pragma unroll
        for (int kk = 0; kk < 4; kk++) {
            int c = kk * 16 + qc * 2;
            float2 v0 = *(const float2*)(xa + c);
            float2 v1 = *(const float2*)(xb + c);
            float2 v2 = *(const float2*)(xa + c + 8);
            float2 v3 = *(const float2*)(xb + c + 8);
            A1[t][kk][0] = pack_bf16x2(v0.x, v0.y);
            A1[t][kk][1] = pack_bf16x2(v1.x, v1.y);
            A1[t][kk][2] = pack_bf16x2(v2.x, v2.y);
            A1[t][kk][3] = pack_bf16x2(v3.x, v3.y);
        }
    }

    // ---- layer 1 ----
    float h1[2][8][4];
    moe_layer2(h1, A1, ws0, cs, lane);

    // ---- h fragments ARE layer-2 A fragments ----
    uint32_t A2[2][4][4];
#pragma unroll
    for (int t = 0; t < 2; t++)
#pragma unroll
        for (int kk = 0; kk < 4; kk++) {
            A2[t][kk][0] = pack_bf16x2(h1[t][2 * kk][0],     h1[t][2 * kk][1]);
            A2[t][kk][1] = pack_bf16x2(h1[t][2 * kk][2],     h1[t][2 * kk][3]);
            A2[t][kk][2] = pack_bf16x2(h1[t][2 * kk + 1][0], h1[t][2 * kk + 1][1]);
            A2[t][kk][3] = pack_bf16x2(h1[t][2 * kk + 1][2], h1[t][2 * kk + 1][3]);
        }

    // ---- layer 2 ----
    float h2[2][8][4];
    moe_layer2(h2, A2, ws1, cs + 256, lane);

    // ---- residual (exact fp32) + store ----
#pragma unroll
    for (int t = 0; t < 2; t++) {
        int rowa = tokbase + t * 16 + qr;
        int rowb = rowa + 8;
        bool va = rowa < Ntok;
        bool vb = rowb < Ntok;
#pragma unroll
        for (int s = 0; s < 8; s++) {
            int f = s * 8 + qc * 2;
            if (va) {
                float2 xr = *(const float2*)(x + (size_t)rowa * DD + f);
                float2 o;
                o.x = h2[t][s][0] + xr.x;
                o.y = h2[t][s][1] + xr.y;
                *(float2*)(out + (size_t)rowa * DD + f) = o;
            }
            if (vb) {
                float2 xr = *(const float2*)(x + (size_t)rowb * DD + f);
                float2 o;
                o.x = h2[t][s][2] + xr.x;
                o.y = h2[t][s][3] + xr.y;
                *(float2*)(out + (size_t)rowb * DD + f) = o;
            }
        }
    }
}

// ------------------------------ launch -------------------------------------
extern "C" void kernel_launch(void* const* d_in, const int* in_sizes, int n_in,
                              void* d_out, int out_size) {
    const float* x    = (const float*)d_in[0];
    const float* wg_a = (const float*)d_in[1];
    const float* we_a = (const float*)d_in[2];
    const float* be_a = (const float*)d_in[3];
    const float* wg_b = (const float*)d_in[4];
    const float* we_b = (const float*)d_in[5];
    const float* be_b = (const float*)d_in[6];
    const int Ntok = in_sizes[0] / DD;

    prep_kernel<<<2, 256>>>(wg_a, we_a, be_a, wg_b, we_b, be_b);

    const int smem_bytes = 2 * NW * WS_U2 * (int)sizeof(uint2) + 512 * (int)sizeof(float);
    cudaFuncSetAttribute(moe_main_kernel, cudaFuncAttributeMaxDynamicSharedMemorySize, smem_bytes);

    const int grid = (Ntok + 255) / 256;
    moe_main_kernel<<<grid, 256, smem_bytes>>>(x, (float*)d_out, Ntok);
}